// round 8
// baseline (speedup 1.0000x reference)
#include <cuda_runtime.h>
#include <cuda_fp16.h>
#include <cstdint>
#include <math.h>

// Problem constants
#define B_  2
#define S_  2048
#define D_  2048
#define H_  16
#define DH  128
#define MROWS (B_ * S_)          // 4096

// ---------------------------------------------------------------------------
// Scratch (static __device__ arrays; no allocation anywhere)
// ---------------------------------------------------------------------------
__device__ float g_tq[(size_t)MROWS * D_];
__device__ float g_tk[(size_t)MROWS * D_];
__device__ float g_tv[(size_t)MROWS * D_];

__device__ __align__(256) __half g_xh [(size_t)MROWS * D_];
__device__ __align__(256) __half g_xl [(size_t)MROWS * D_];
__device__ __align__(256) __half g_qwh[(size_t)D_ * D_];
__device__ __align__(256) __half g_qwl[(size_t)D_ * D_];
__device__ __align__(256) __half g_kwh[(size_t)D_ * D_];
__device__ __align__(256) __half g_kwl[(size_t)D_ * D_];
__device__ __align__(256) __half g_vwh[(size_t)D_ * D_];
__device__ __align__(256) __half g_vwl[(size_t)D_ * D_];
__device__ __align__(256) __half g_owh[(size_t)D_ * D_];
__device__ __align__(256) __half g_owl[(size_t)D_ * D_];
__device__ __align__(256) __half g_qh [(size_t)B_ * H_ * S_ * DH];
__device__ __align__(256) __half g_ql [(size_t)B_ * H_ * S_ * DH];
__device__ __align__(256) __half g_kh [(size_t)B_ * H_ * S_ * DH];
__device__ __align__(256) __half g_kl [(size_t)B_ * H_ * S_ * DH];
__device__ __align__(256) __half g_vth[(size_t)B_ * H_ * DH * S_];   // V^T [B,H,Dh,S]
__device__ __align__(256) __half g_vtl[(size_t)B_ * H_ * DH * S_];
__device__ __align__(256) __half g_ctxh[(size_t)MROWS * D_];
__device__ __align__(256) __half g_ctxl[(size_t)MROWS * D_];

// ---------------------------------------------------------------------------
// Helpers (all sm_80-era instructions: valid on base sm_103 target)
// ---------------------------------------------------------------------------
#define SWZ(x) ((x) ^ (((x) >> 3) & 0x70))

#define LDSM4(r, addr) \
    asm volatile("ldmatrix.sync.aligned.m8n8.x4.shared.b16 {%0,%1,%2,%3}, [%4];" \
        : "=r"((r)[0]), "=r"((r)[1]), "=r"((r)[2]), "=r"((r)[3]) : "r"(addr))

// fp32-accumulate MMA (main hi*hi pass)
#define MMA(d, a, b0, b1) \
    asm volatile("mma.sync.aligned.m16n8k16.row.col.f32.f16.f16.f32 " \
        "{%0,%1,%2,%3},{%4,%5,%6,%7},{%8,%9},{%0,%1,%2,%3};" \
        : "+f"((d)[0]), "+f"((d)[1]), "+f"((d)[2]), "+f"((d)[3]) \
        : "r"((a)[0]), "r"((a)[1]), "r"((a)[2]), "r"((a)[3]), "r"(b0), "r"(b1))

// fp16-accumulate MMA (2x rate; used for the small correction passes)
#define MMA16(d, a, b0, b1) \
    asm volatile("mma.sync.aligned.m16n8k16.row.col.f16.f16.f16.f16 " \
        "{%0,%1},{%2,%3,%4,%5},{%6,%7},{%0,%1};" \
        : "+r"((d)[0]), "+r"((d)[1]) \
        : "r"((a)[0]), "r"((a)[1]), "r"((a)[2]), "r"((a)[3]), "r"(b0), "r"(b1))

#define CP16(dst, src) \
    asm volatile("cp.async.cg.shared.global [%0], [%1], 16;" :: "r"(dst), "l"(src))
#define CP_COMMIT() asm volatile("cp.async.commit_group;" ::: "memory")
#define CP_WAIT0()  asm volatile("cp.async.wait_group 0;"  ::: "memory")

__device__ __forceinline__ void split2(float x, __half& h, __half& l) {
    h = __float2half(x);
    l = __float2half(x - __half2float(h));
}
__device__ __forceinline__ uint32_t packh2(__half a, __half b) {
    __half2 t; t.x = a; t.y = b;
    return *(uint32_t*)&t;
}
__device__ __forceinline__ float2 h2f2(uint32_t u) {
    return __half22float2(*(__half2*)&u);
}

// ---------------------------------------------------------------------------
// fp16-split HMMA GEMM.  C = scale * (A @ B^T) + bias, fp32 out
//   hi*hi in fp32 accum; hi*lo + lo*hi share one fp16x2 accum (2x-rate MMA).
//   Inner loop issues each accumulator's dependent MMA16 pair in SEPARATE
//   passes so the RAW pair is split by 15 independent MMAs (stall removal).
// Block 128x128, BK=64; 8 warps of 64x32; cp.async double buffer.
// ---------------------------------------------------------------------------
__global__ __launch_bounds__(256, 1)
void gemm_hs(const __half* __restrict__ Ah, const __half* __restrict__ Al,
             const __half* __restrict__ Bh, const __half* __restrict__ Bl,
             float* __restrict__ C, int K, int ldb,
             const float* __restrict__ bias, float scale)
{
    extern __shared__ char smem[];
    const uint32_t sb = (uint32_t)__cvta_generic_to_shared(smem);

    const int tid = threadIdx.x, wid = tid >> 5, lane = tid & 31;
    const long bm = (long)blockIdx.y * 128;
    const long bn = (long)blockIdx.x * 128;

    const int srow = tid >> 1;
    const int sc0  = (tid & 1) * 4;
    uint32_t soff[4];
#pragma unroll
    for (int i = 0; i < 4; i++)
        soff[i] = SWZ((uint32_t)(srow * 128 + (sc0 + i) * 16));

    const int nk = K / 64;

    // prologue: stage buffer 0
    {
        const __half* pa = Ah + (bm + srow) * (long)K + sc0 * 8;
        const __half* pl = Al + (bm + srow) * (long)K + sc0 * 8;
        const __half* pb  = Bh + (bn + srow) * (long)ldb + sc0 * 8;
        const __half* pbl = Bl + (bn + srow) * (long)ldb + sc0 * 8;
#pragma unroll
        for (int i = 0; i < 4; i++) {
            CP16(sb + soff[i],         pa + i * 8);
            CP16(sb + 16384 + soff[i], pl + i * 8);
            CP16(sb + 32768 + soff[i], pb + i * 8);
            CP16(sb + 49152 + soff[i], pbl + i * 8);
        }
        CP_COMMIT();
    }

    float acc[4][4][4];
    uint32_t acc16[4][4][2];
#pragma unroll
    for (int a = 0; a < 4; a++)
#pragma unroll
        for (int b = 0; b < 4; b++) {
#pragma unroll
            for (int c = 0; c < 4; c++) acc[a][b][c] = 0.f;
            acc16[a][b][0] = 0u; acc16[a][b][1] = 0u;
        }

    const int m0 = (wid & 1) * 64;
    const int n0 = (wid >> 1) * 32;
    const int rA = lane & 15;
    const int cA = lane >> 4;
    const int rB = ((lane >> 1) & 8) + (lane & 7);
    const int cB = (lane >> 3) & 1;

    for (int kt = 0; kt < nk; ++kt) {
        const int s = kt & 1;
        CP_WAIT0();
        __syncthreads();

        if (kt + 1 < nk) {
            const uint32_t db = sb + (s ^ 1) * 65536;
            const __half* pa = Ah + (bm + srow) * (long)K + (kt + 1) * 64 + sc0 * 8;
            const __half* pl = Al + (bm + srow) * (long)K + (kt + 1) * 64 + sc0 * 8;
            const __half* pb  = Bh + (bn + srow) * (long)ldb + (kt + 1) * 64 + sc0 * 8;
            const __half* pbl = Bl + (bn + srow) * (long)ldb + (kt + 1) * 64 + sc0 * 8;
#pragma unroll
            for (int i = 0; i < 4; i++) {
                CP16(db + soff[i],         pa + i * 8);
                CP16(db + 16384 + soff[i], pl + i * 8);
                CP16(db + 32768 + soff[i], pb + i * 8);
                CP16(db + 49152 + soff[i], pbl + i * 8);
            }
            CP_COMMIT();
        }

        const uint32_t ba = sb + (uint32_t)s * 65536;
#pragma unroll
        for (int ks = 0; ks < 4; ks++) {
            uint32_t ah[4][4], al[4][4], bh[2][4], bl[2][4];
#pragma unroll
            for (int mt = 0; mt < 4; mt++) {
                const uint32_t addr = ba +
                    SWZ((uint32_t)((m0 + mt * 16 + rA) * 128 + (ks * 2 + cA) * 16));
                LDSM4(ah[mt], addr);
                LDSM4(al[mt], addr + 16384);
            }
#pragma unroll
            for (int p = 0; p < 2; p++) {
                const uint32_t addr = ba + 32768 +
                    SWZ((uint32_t)((n0 + p * 16 + rB) * 128 + (ks * 2 + cB) * 16));
                LDSM4(bh[p], addr);
                LDSM4(bl[p], addr + 16384);
            }
            // pass 1: hi*hi (fp32 acc) — 16 independent accumulators
#pragma unroll
            for (int mt = 0; mt < 4; mt++)
#pragma unroll
                for (int nt = 0; nt < 4; nt++) {
                    const int p = nt >> 1, q = (nt & 1) * 2;
                    MMA(acc[mt][nt], ah[mt], bh[p][q], bh[p][q + 1]);
                }
            // pass 2: hi*lo (fp16 acc)
#pragma unroll
            for (int mt = 0; mt < 4; mt++)
#pragma unroll
                for (int nt = 0; nt < 4; nt++) {
                    const int p = nt >> 1, q = (nt & 1) * 2;
                    MMA16(acc16[mt][nt], ah[mt], bl[p][q], bl[p][q + 1]);
                }
            // pass 3: lo*hi (fp16 acc) — RAW pair now 16 ops apart
#pragma unroll
            for (int mt = 0; mt < 4; mt++)
#pragma unroll
                for (int nt = 0; nt < 4; nt++) {
                    const int p = nt >> 1, q = (nt & 1) * 2;
                    MMA16(acc16[mt][nt], al[mt], bh[p][q], bh[p][q + 1]);
                }
        }
    }

    const int g = lane >> 2, t = lane & 3;
#pragma unroll
    for (int mt = 0; mt < 4; mt++) {
        const long r0 = bm + m0 + mt * 16 + g;
#pragma unroll
        for (int nt = 0; nt < 4; nt++) {
            const long col = bn + n0 + nt * 8 + 2 * t;
            const float2 u = h2f2(acc16[mt][nt][0]);
            const float2 w = h2f2(acc16[mt][nt][1]);
            float c0 = (acc[mt][nt][0] + u.x) * scale;
            float c1 = (acc[mt][nt][1] + u.y) * scale;
            float c2 = (acc[mt][nt][2] + w.x) * scale;
            float c3 = (acc[mt][nt][3] + w.y) * scale;
            if (bias) {
                const float b0 = __ldg(bias + col), b1 = __ldg(bias + col + 1);
                c0 += b0; c1 += b1; c2 += b0; c3 += b1;
            }
            *(float2*)(C + r0 * (long)D_ + col)       = make_float2(c0, c1);
            *(float2*)(C + (r0 + 8) * (long)D_ + col) = make_float2(c2, c3);
        }
    }
}

// ---------------------------------------------------------------------------
// Flash attention: per CTA = 128 Q rows x one (b,h).
// hi*hi in fp32; corrections in fp16x2 accumulators (2x-rate MMA).
// QK corrections use pass-split ordering; PV corrections use two separate
// accumulators (o16a: Ph*Vl, o16b: Pl*Vh) to kill same-acc RAW stalls.
// smem: Q 64K | Kbuf 2x32K | Vbuf 2x32K = 192K.
// ---------------------------------------------------------------------------
#define NKV (S_ / 64)     // 32 chunks

__global__ __launch_bounds__(256, 1)
void flash_kernel(const __half* __restrict__ Qh, const __half* __restrict__ Ql,
                  const __half* __restrict__ Kh, const __half* __restrict__ Kl,
                  const __half* __restrict__ Vth, const __half* __restrict__ Vtl,
                  __half* __restrict__ Ch, __half* __restrict__ Cl)
{
    extern __shared__ char smem[];
    const uint32_t sb = (uint32_t)__cvta_generic_to_shared(smem);

    const int tid = threadIdx.x, wid = tid >> 5, lane = tid & 31;
    const int qt = blockIdx.x;       // q tile (16)
    const int bh = blockIdx.y;       // b*H + h (32)
    const int b  = bh >> 4, h = bh & 15;

    const __half* Qhp = Qh + ((long)bh * S_ + (long)qt * 128) * DH;
    const __half* Qlp = Ql + ((long)bh * S_ + (long)qt * 128) * DH;
    const __half* Khp = Kh + (long)bh * S_ * DH;
    const __half* Klp = Kl + (long)bh * S_ * DH;
    const __half* Vhp = Vth + (long)bh * DH * S_;
    const __half* Vlp = Vtl + (long)bh * DH * S_;

    const uint32_t KBUF0 = 65536, VBUF0 = 131072;

    // ---- prologue: stage Q ----
    {
        const int r = tid >> 1, c0 = (tid & 1) * 8;
        const __half* s1 = Qhp + (long)r * DH;
        const __half* s2 = Qlp + (long)r * DH;
#pragma unroll
        for (int j = 0; j < 8; j++) {
            const int c = c0 + j;
            const uint32_t d = sb + ((c >= 8) ? 16384u : 0u) +
                               SWZ((uint32_t)(r * 128 + (c & 7) * 16));
            CP16(d,          s1 + c * 8);
            CP16(d + 32768u, s2 + c * 8);
        }
    }
    auto stageKV = [&](int it, uint32_t kdst, uint32_t vdst) {
        {
            const int r = tid >> 2, c0 = (tid & 3) * 4;
            const __half* s1 = Khp + ((long)it * 64 + r) * DH;
            const __half* s2 = Klp + ((long)it * 64 + r) * DH;
#pragma unroll
            for (int j = 0; j < 4; j++) {
                const int c = c0 + j;
                const uint32_t d = kdst + ((c >= 8) ? 8192u : 0u) +
                                   SWZ((uint32_t)(r * 128 + (c & 7) * 16));
                CP16(d,          s1 + c * 8);
                CP16(d + 16384u, s2 + c * 8);
            }
        }
        {
            const int dd = tid >> 1, c0 = (tid & 1) * 4;
            const __half* s1 = Vhp + (long)dd * S_ + it * 64;
            const __half* s2 = Vlp + (long)dd * S_ + it * 64;
#pragma unroll
            for (int j = 0; j < 4; j++) {
                const int c = c0 + j;
                const uint32_t d = vdst + SWZ((uint32_t)(dd * 128 + c * 16));
                CP16(d,          s1 + c * 8);
                CP16(d + 16384u, s2 + c * 8);
            }
        }
    };
    stageKV(0, sb + KBUF0, sb + VBUF0);
    CP_COMMIT();

    const int wm = wid * 16;
    const int rA = lane & 15;
    const int cA = lane >> 4;
    const int rB = ((lane >> 1) & 8) + (lane & 7);
    const int cB = (lane >> 3) & 1;
    const int g = lane >> 2, t = lane & 3;

    float o[16][4];
    uint32_t o16a[16][2], o16b[16][2];
#pragma unroll
    for (int i = 0; i < 16; i++) {
#pragma unroll
        for (int j = 0; j < 4; j++) o[i][j] = 0.f;
        o16a[i][0] = 0u; o16a[i][1] = 0u;
        o16b[i][0] = 0u; o16b[i][1] = 0u;
    }
    float m0 = -INFINITY, m1 = -INFINITY, l0 = 0.f, l1 = 0.f;

    for (int it = 0; it < NKV; ++it) {
        const int s = it & 1;
        CP_WAIT0();
        __syncthreads();
        if (it + 1 < NKV) {
            const int s2 = s ^ 1;
            stageKV(it + 1, sb + KBUF0 + s2 * 32768u, sb + VBUF0 + s2 * 32768u);
            CP_COMMIT();
        }

        const uint32_t kbuf = sb + KBUF0 + (uint32_t)s * 32768u;
        const uint32_t vbuf = sb + VBUF0 + (uint32_t)s * 32768u;

        // ---- S = Q' K^T ----
        float sa[8][4];
        uint32_t sa16[8][2];
#pragma unroll
        for (int i = 0; i < 8; i++) {
#pragma unroll
            for (int j = 0; j < 4; j++) sa[i][j] = 0.f;
            sa16[i][0] = 0u; sa16[i][1] = 0u;
        }

#pragma unroll
        for (int ks = 0; ks < 8; ks++) {
            uint32_t ah[4], al[4], bh[4][4], bl[4][4];
            const uint32_t qa = sb + (ks >> 2) * 16384u +
                SWZ((uint32_t)((wm + rA) * 128 + ((ks & 3) * 2 + cA) * 16));
            LDSM4(ah, qa);
            LDSM4(al, qa + 32768u);
            const uint32_t kb2 = kbuf + (ks >> 2) * 8192u;
#pragma unroll
            for (int p = 0; p < 4; p++) {
                const uint32_t addr = kb2 +
                    SWZ((uint32_t)((p * 16 + rB) * 128 + ((ks & 3) * 2 + cB) * 16));
                LDSM4(bh[p], addr);
                LDSM4(bl[p], addr + 16384u);
            }
            // pass 1: hi*hi
#pragma unroll
            for (int nt = 0; nt < 8; nt++) {
                const int p = nt >> 1, q = (nt & 1) * 2;
                MMA(sa[nt], ah, bh[p][q], bh[p][q + 1]);
            }
            // pass 2: hi*lo
#pragma unroll
            for (int nt = 0; nt < 8; nt++) {
                const int p = nt >> 1, q = (nt & 1) * 2;
                MMA16(sa16[nt], ah, bl[p][q], bl[p][q + 1]);
            }
            // pass 3: lo*hi
#pragma unroll
            for (int nt = 0; nt < 8; nt++) {
                const int p = nt >> 1, q = (nt & 1) * 2;
                MMA16(sa16[nt], al, bh[p][q], bh[p][q + 1]);
            }
        }

        // merge fp16 corrections into fp32 scores
#pragma unroll
        for (int nt = 0; nt < 8; nt++) {
            const float2 u = h2f2(sa16[nt][0]);
            const float2 w = h2f2(sa16[nt][1]);
            sa[nt][0] += u.x; sa[nt][1] += u.y;
            sa[nt][2] += w.x; sa[nt][3] += w.y;
        }

        // ---- online softmax (rows g and g+8) ----
        float nm0 = sa[0][0], nm1 = sa[0][2];
#pragma unroll
        for (int nt = 0; nt < 8; nt++) {
            nm0 = fmaxf(nm0, fmaxf(sa[nt][0], sa[nt][1]));
            nm1 = fmaxf(nm1, fmaxf(sa[nt][2], sa[nt][3]));
        }
        nm0 = fmaxf(nm0, __shfl_xor_sync(0xFFFFFFFFu, nm0, 1));
        nm0 = fmaxf(nm0, __shfl_xor_sync(0xFFFFFFFFu, nm0, 2));
        nm1 = fmaxf(nm1, __shfl_xor_sync(0xFFFFFFFFu, nm1, 1));
        nm1 = fmaxf(nm1, __shfl_xor_sync(0xFFFFFFFFu, nm1, 2));

        const float mn0 = fmaxf(m0, nm0), mn1 = fmaxf(m1, nm1);
        const float al0 = exp2f(m0 - mn0), al1 = exp2f(m1 - mn1);
        m0 = mn0; m1 = mn1;

        float rs0 = 0.f, rs1 = 0.f;
#pragma unroll
        for (int nt = 0; nt < 8; nt++) {
            sa[nt][0] = exp2f(sa[nt][0] - m0);
            sa[nt][1] = exp2f(sa[nt][1] - m0);
            sa[nt][2] = exp2f(sa[nt][2] - m1);
            sa[nt][3] = exp2f(sa[nt][3] - m1);
            rs0 += sa[nt][0] + sa[nt][1];
            rs1 += sa[nt][2] + sa[nt][3];
        }
        rs0 += __shfl_xor_sync(0xFFFFFFFFu, rs0, 1);
        rs0 += __shfl_xor_sync(0xFFFFFFFFu, rs0, 2);
        rs1 += __shfl_xor_sync(0xFFFFFFFFu, rs1, 1);
        rs1 += __shfl_xor_sync(0xFFFFFFFFu, rs1, 2);
        l0 = l0 * al0 + rs0;
        l1 = l1 * al1 + rs1;

        // rescale fp32 O and both fp16 correction accumulators
        {
            const __half2 a0 = __half2half2(__float2half(al0));
            const __half2 a1 = __half2half2(__float2half(al1));
#pragma unroll
            for (int nt = 0; nt < 16; nt++) {
                o[nt][0] *= al0; o[nt][1] *= al0;
                o[nt][2] *= al1; o[nt][3] *= al1;
                __half2 ta0 = __hmul2(*(__half2*)&o16a[nt][0], a0);
                __half2 ta1 = __hmul2(*(__half2*)&o16a[nt][1], a1);
                __half2 tb0 = __hmul2(*(__half2*)&o16b[nt][0], a0);
                __half2 tb1 = __hmul2(*(__half2*)&o16b[nt][1], a1);
                o16a[nt][0] = *(uint32_t*)&ta0;
                o16a[nt][1] = *(uint32_t*)&ta1;
                o16b[nt][0] = *(uint32_t*)&tb0;
                o16b[nt][1] = *(uint32_t*)&tb1;
            }
        }

        // ---- O += P V ----
#pragma unroll
        for (int kb = 0; kb < 4; kb++) {
            uint32_t aPh[4], aPl[4];
            {
                const float p00 = sa[2 * kb][0],     p01 = sa[2 * kb][1];
                const float p10 = sa[2 * kb][2],     p11 = sa[2 * kb][3];
                const float q00 = sa[2 * kb + 1][0], q01 = sa[2 * kb + 1][1];
                const float q10 = sa[2 * kb + 1][2], q11 = sa[2 * kb + 1][3];
                __half hA, lA, hB, lB;
                split2(p00, hA, lA); split2(p01, hB, lB);
                aPh[0] = packh2(hA, hB); aPl[0] = packh2(lA, lB);
                split2(p10, hA, lA); split2(p11, hB, lB);
                aPh[1] = packh2(hA, hB); aPl[1] = packh2(lA, lB);
                split2(q00, hA, lA); split2(q01, hB, lB);
                aPh[2] = packh2(hA, hB); aPl[2] = packh2(lA, lB);
                split2(q10, hA, lA); split2(q11, hB, lB);
                aPh[3] = packh2(hA, hB); aPl[3] = packh2(lA, lB);
            }
#pragma unroll
            for (int pp = 0; pp < 8; pp++) {
                uint32_t vb[4], vbl[4];
                const uint32_t addr = vbuf +
                    SWZ((uint32_t)((pp * 16 + rB) * 128 + (kb * 2 + cB) * 16));
                LDSM4(vb, addr);
                LDSM4(vbl, addr + 16384u);
                MMA(o[pp * 2], aPh, vb[0], vb[1]);
                MMA16(o16a[pp * 2], aPh, vbl[0], vbl[1]);
                MMA16(o16b[pp * 2], aPl, vb[0], vb[1]);
                MMA(o[pp * 2 + 1], aPh, vb[2], vb[3]);
                MMA16(o16a[pp * 2 + 1], aPh, vbl[2], vbl[3]);
                MMA16(o16b[pp * 2 + 1], aPl, vb[2], vb[3]);
            }
        }
    }

    // ---- epilogue: merge corrections, normalize, split, store [B,S,D] ----
    const float r0i = 1.0f / l0, r1i = 1.0f / l1;
    const long row0 = (long)b * S_ + (long)qt * 128 + wm + g;
    const long row1 = row0 + 8;
#pragma unroll
    for (int nt = 0; nt < 16; nt++) {
        const long col = (long)h * DH + nt * 8 + 2 * t;
        const float2 ua = h2f2(o16a[nt][0]);
        const float2 wa = h2f2(o16a[nt][1]);
        const float2 ub = h2f2(o16b[nt][0]);
        const float2 wb = h2f2(o16b[nt][1]);
        const float c00 = (o[nt][0] + ua.x + ub.x) * r0i;
        const float c01 = (o[nt][1] + ua.y + ub.y) * r0i;
        const float c10 = (o[nt][2] + wa.x + wb.x) * r1i;
        const float c11 = (o[nt][3] + wa.y + wb.y) * r1i;
        __half hA, lA, hB, lB;
        split2(c00, hA, lA); split2(c01, hB, lB);
        *(uint32_t*)(Ch + row0 * D_ + col) = packh2(hA, hB);
        *(uint32_t*)(Cl + row0 * D_ + col) = packh2(lA, lB);
        split2(c10, hA, lA); split2(c11, hB, lB);
        *(uint32_t*)(Ch + row1 * D_ + col) = packh2(hA, hB);
        *(uint32_t*)(Cl + row1 * D_ + col) = packh2(lA, lB);
    }
}

// ---------------------------------------------------------------------------
// Fused fp32 -> fp16 hi/lo split for x + 4 weight matrices (one launch).
// ---------------------------------------------------------------------------
__global__ __launch_bounds__(256)
void split_all_kernel(const float* __restrict__ x,
                      const float* __restrict__ qw, const float* __restrict__ kw,
                      const float* __restrict__ vw, const float* __restrict__ ow)
{
    const float* src;
    __half *oh, *ol;
    long n;
    switch (blockIdx.y) {
        case 0: src = x;  oh = g_xh;  ol = g_xl;  n = (long)MROWS * D_; break;
        case 1: src = qw; oh = g_qwh; ol = g_qwl; n = (long)D_ * D_;    break;
        case 2: src = kw; oh = g_kwh; ol = g_kwl; n = (long)D_ * D_;    break;
        case 3: src = vw; oh = g_vwh; ol = g_vwl; n = (long)D_ * D_;    break;
        default: src = ow; oh = g_owh; ol = g_owl; n = (long)D_ * D_;   break;
    }
    const long i = ((long)blockIdx.x * blockDim.x + threadIdx.x) * 4;
    if (i >= n) return;
    float4 v = *(const float4*)(src + i);
    __half h0, l0, h1, l1, h2, l2, h3, l3;
    split2(v.x, h0, l0); split2(v.y, h1, l1);
    split2(v.z, h2, l2); split2(v.w, h3, l3);
    *(uint32_t*)(oh + i)     = packh2(h0, h1);
    *(uint32_t*)(oh + i + 2) = packh2(h2, h3);
    *(uint32_t*)(ol + i)     = packh2(l0, l1);
    *(uint32_t*)(ol + i + 2) = packh2(l2, l3);
}

// ---------------------------------------------------------------------------
// Fused RoPE(+permute, split) for q,k  AND  V transpose/split.
// ---------------------------------------------------------------------------
#define RB ((B_ * H_ * S_ * (DH / 2)) / 256)      // 16384 rope blocks
#define VB ((S_ / 32) * (DH / 32) * (B_ * H_))    // 8192 vtrans blocks

__global__ __launch_bounds__(256)
void rope_vtrans_kernel()
{
    __shared__ float tile[32][33];
    const int bid = blockIdx.x;

    if (bid < RB) {
        const int HALF = DH / 2;
        const long idx = (long)bid * 256 + threadIdx.x;

        const int j = (int)(idx % HALF);
        const int s = (int)((idx / HALF) % S_);
        const int h = (int)((idx / ((long)HALF * S_)) % H_);
        const int b = (int)(idx / ((long)HALF * S_ * H_));

        const long off_in  = ((long)(b * S_ + s)) * D_ + h * DH + j;
        const long off_out = (((long)(b * H_ + h) * S_) + s) * DH + j;

        const float inv = expf(-(float)j * (9.210340371976184f / 64.0f));
        const float th  = (float)s * inv;
        const float c  = cosf(th);
        const float sn = sinf(th);

        const float QS = 0.08838834764831845f * 1.4426950408889634f; // scale*log2e

        {
            const float x1 = g_tq[off_in];
            const float x2 = g_tq[off_in + HALF];
            const float o1 = (x1 * c - x2 * sn) * QS;
            const float o2 = (x2 * c + x1 * sn) * QS;
            __half hh, hl;
            split2(o1, hh, hl); g_qh[off_out] = hh;        g_ql[off_out] = hl;
            split2(o2, hh, hl); g_qh[off_out + HALF] = hh; g_ql[off_out + HALF] = hl;
        }
        {
            const float x1 = g_tk[off_in];
            const float x2 = g_tk[off_in + HALF];
            const float o1 = x1 * c - x2 * sn;
            const float o2 = x2 * c + x1 * sn;
            __half hh, hl;
            split2(o1, hh, hl); g_kh[off_out] = hh;        g_kl[off_out] = hl;
            split2(o2, hh, hl); g_kh[off_out + HALF] = hh; g_kl[off_out + HALF] = hl;
        }
    } else {
        const int vb = bid - RB;
        const int sblk = vb % (S_ / 32);
        const int dblk = (vb / (S_ / 32)) % (DH / 32);
        const int bhz  = vb / ((S_ / 32) * (DH / 32));
        const int b = bhz >> 4, h = bhz & 15;
        const int s0 = sblk * 32, d0 = dblk * 32;
        const int tx = threadIdx.x & 31, ty = threadIdx.x >> 5;

#pragma unroll
        for (int r = 0; r < 4; r++) {
            const int s = s0 + ty + r * 8;
            tile[ty + r * 8][tx] =
                g_tv[((long)b * S_ + s) * D_ + h * DH + d0 + tx];
        }
        __syncthreads();

#pragma unroll
        for (int r = 0; r < 4; r++) {
            const int d = d0 + ty + r * 8;
            const float v = tile[tx][ty + r * 8];
            __half hh, hl;
            split2(v, hh, hl);
            const long off = ((long)bhz * DH + d) * S_ + s0 + tx;
            g_vth[off] = hh;
            g_vtl[off] = hl;
        }
    }
}

// ---------------------------------------------------------------------------
// Launch
// ---------------------------------------------------------------------------
extern "C" void kernel_launch(void* const* d_in, const int* in_sizes, int n_in,
                              void* d_out, int out_size)
{
    const float* x  = (const float*)d_in[0];
    const float* qw = (const float*)d_in[1];
    const float* kw = (const float*)d_in[2];
    const float* vw = (const float*)d_in[3];
    const float* qb = (const float*)d_in[4];
    const float* kb = (const float*)d_in[5];
    const float* vb = (const float*)d_in[6];
    const float* ow = (const float*)d_in[7];
    const float* ob = (const float*)d_in[8];
    float* out = (float*)d_out;

    float *tq, *tk, *tv;
    __half *xh, *xl, *qwh, *qwl, *kwh, *kwl, *vwh, *vwl, *owh, *owl;
    __half *qh, *ql, *kh, *kl, *vth, *vtl, *ctxh, *ctxl;
    cudaGetSymbolAddress((void**)&tq,  g_tq);
    cudaGetSymbolAddress((void**)&tk,  g_tk);
    cudaGetSymbolAddress((void**)&tv,  g_tv);
    cudaGetSymbolAddress((void**)&xh,  g_xh);
    cudaGetSymbolAddress((void**)&xl,  g_xl);
    cudaGetSymbolAddress((void**)&qwh, g_qwh);
    cudaGetSymbolAddress((void**)&qwl, g_qwl);
    cudaGetSymbolAddress((void**)&kwh, g_kwh);
    cudaGetSymbolAddress((void**)&kwl, g_kwl);
    cudaGetSymbolAddress((void**)&vwh, g_vwh);
    cudaGetSymbolAddress((void**)&vwl, g_vwl);
    cudaGetSymbolAddress((void**)&owh, g_owh);
    cudaGetSymbolAddress((void**)&owl, g_owl);
    cudaGetSymbolAddress((void**)&qh,  g_qh);
    cudaGetSymbolAddress((void**)&ql,  g_ql);
    cudaGetSymbolAddress((void**)&kh,  g_kh);
    cudaGetSymbolAddress((void**)&kl,  g_kl);
    cudaGetSymbolAddress((void**)&vth, g_vth);
    cudaGetSymbolAddress((void**)&vtl, g_vtl);
    cudaGetSymbolAddress((void**)&ctxh, g_ctxh);
    cudaGetSymbolAddress((void**)&ctxl, g_ctxl);

    const int SMEM_G = 131072;
    const int SMEM_F = 196608;
    cudaFuncSetAttribute(gemm_hs,      cudaFuncAttributeMaxDynamicSharedMemorySize, SMEM_G);
    cudaFuncSetAttribute(flash_kernel, cudaFuncAttributeMaxDynamicSharedMemorySize, SMEM_F);

    const dim3 blk(256);

    // 0: split fp32 inputs to fp16 hi/lo (one fused launch)
    {
        const long nx = (long)MROWS * D_;
        dim3 grid((unsigned)(nx / 4 / 256), 5);
        split_all_kernel<<<grid, blk>>>(x, qw, kw, vw, ow);
    }

    // 1-3: Q/K/V projections (M=4096, N=2048, K=2048), fp32 out
    {
        dim3 grid(D_ / 128, MROWS / 128, 1);
        gemm_hs<<<grid, blk, SMEM_G>>>(xh, xl, qwh, qwl, tq, D_, D_, qb, 1.0f);
        gemm_hs<<<grid, blk, SMEM_G>>>(xh, xl, kwh, kwl, tk, D_, D_, kb, 1.0f);
        gemm_hs<<<grid, blk, SMEM_G>>>(xh, xl, vwh, vwl, tv, D_, D_, vb, 1.0f);
    }

    // 4: RoPE (q,k) + permute/split  AND  V transpose/split (one launch)
    rope_vtrans_kernel<<<RB + VB, blk>>>();

    // 5: fused flash attention -> ctx split fp16 [B,S,D]
    {
        dim3 grid(S_ / 128, B_ * H_);
        flash_kernel<<<grid, blk, SMEM_F>>>(qh, ql, kh, kl, vth, vtl, ctxh, ctxl);
    }

    // 6: out = ctx @ out_w^T + out_b (fp32 out)
    {
        dim3 grid(D_ / 128, MROWS / 128, 1);
        gemm_hs<<<grid, blk, SMEM_G>>>(ctxh, ctxl, owh, owl, out, D_, D_, ob, 1.0f);
    }
}

// round 10
// speedup vs baseline: 1.1222x; 1.1222x over previous
#include <cuda_runtime.h>
#include <cuda_fp16.h>
#include <cstdint>
#include <math.h>

// Problem constants
#define B_  2
#define S_  2048
#define D_  2048
#define H_  16
#define DH  128
#define MROWS (B_ * S_)          // 4096

// ---------------------------------------------------------------------------
// Scratch (static __device__ arrays; no allocation anywhere)
// ---------------------------------------------------------------------------
__device__ float g_tq[(size_t)MROWS * D_];
__device__ float g_tk[(size_t)MROWS * D_];
__device__ float g_tv[(size_t)MROWS * D_];

__device__ __align__(256) __half g_xh [(size_t)MROWS * D_];
__device__ __align__(256) __half g_xl [(size_t)MROWS * D_];
__device__ __align__(256) __half g_qwh[(size_t)D_ * D_];
__device__ __align__(256) __half g_qwl[(size_t)D_ * D_];
__device__ __align__(256) __half g_kwh[(size_t)D_ * D_];
__device__ __align__(256) __half g_kwl[(size_t)D_ * D_];
__device__ __align__(256) __half g_vwh[(size_t)D_ * D_];
__device__ __align__(256) __half g_vwl[(size_t)D_ * D_];
__device__ __align__(256) __half g_owh[(size_t)D_ * D_];
__device__ __align__(256) __half g_owl[(size_t)D_ * D_];
__device__ __align__(256) __half g_qh [(size_t)B_ * H_ * S_ * DH];
__device__ __align__(256) __half g_ql [(size_t)B_ * H_ * S_ * DH];
__device__ __align__(256) __half g_kh [(size_t)B_ * H_ * S_ * DH];
__device__ __align__(256) __half g_kl [(size_t)B_ * H_ * S_ * DH];
__device__ __align__(256) __half g_vth[(size_t)B_ * H_ * DH * S_];   // V^T [B,H,Dh,S]
__device__ __align__(256) __half g_vtl[(size_t)B_ * H_ * DH * S_];
__device__ __align__(256) __half g_ctxh[(size_t)MROWS * D_];
__device__ __align__(256) __half g_ctxl[(size_t)MROWS * D_];

// ---------------------------------------------------------------------------
// Helpers (all sm_80-era instructions: valid on base sm_103 target)
// ---------------------------------------------------------------------------
#define SWZ(x) ((x) ^ (((x) >> 3) & 0x70))

#define LDSM4(r, addr) \
    asm volatile("ldmatrix.sync.aligned.m8n8.x4.shared.b16 {%0,%1,%2,%3}, [%4];" \
        : "=r"((r)[0]), "=r"((r)[1]), "=r"((r)[2]), "=r"((r)[3]) : "r"(addr))

// fp32-accumulate MMA (main hi*hi pass)
#define MMA(d, a, b0, b1) \
    asm volatile("mma.sync.aligned.m16n8k16.row.col.f32.f16.f16.f32 " \
        "{%0,%1,%2,%3},{%4,%5,%6,%7},{%8,%9},{%0,%1,%2,%3};" \
        : "+f"((d)[0]), "+f"((d)[1]), "+f"((d)[2]), "+f"((d)[3]) \
        : "r"((a)[0]), "r"((a)[1]), "r"((a)[2]), "r"((a)[3]), "r"(b0), "r"(b1))

// fp16-accumulate MMA (2x rate; used for the small correction passes)
#define MMA16(d, a, b0, b1) \
    asm volatile("mma.sync.aligned.m16n8k16.row.col.f16.f16.f16.f16 " \
        "{%0,%1},{%2,%3,%4,%5},{%6,%7},{%0,%1};" \
        : "+r"((d)[0]), "+r"((d)[1]) \
        : "r"((a)[0]), "r"((a)[1]), "r"((a)[2]), "r"((a)[3]), "r"(b0), "r"(b1))

#define CP16(dst, src) \
    asm volatile("cp.async.cg.shared.global [%0], [%1], 16;" :: "r"(dst), "l"(src))
#define CP_COMMIT() asm volatile("cp.async.commit_group;" ::: "memory")
#define CP_WAIT0()  asm volatile("cp.async.wait_group 0;"  ::: "memory")

__device__ __forceinline__ void split2(float x, __half& h, __half& l) {
    h = __float2half(x);
    l = __float2half(x - __half2float(h));
}
__device__ __forceinline__ uint32_t packh2(__half a, __half b) {
    __half2 t; t.x = a; t.y = b;
    return *(uint32_t*)&t;
}
__device__ __forceinline__ float2 h2f2(uint32_t u) {
    return __half22float2(*(__half2*)&u);
}

// ---------------------------------------------------------------------------
// fp16-split HMMA GEMM.  C = scale * (A @ B^T) + bias, fp32 out
//   hi*hi in fp32 accum; hi*lo + lo*hi share one fp16x2 accum (2x-rate MMA).
// Block 128x128, BK=64; *16 warps* of 32x32 (4 warps/SMSP for latency hiding);
// cp.async double buffer.  smem: 2 x [Ah 16K | Al 16K | Bh 16K | Bl 16K].
// ---------------------------------------------------------------------------
__global__ __launch_bounds__(512, 1)
void gemm_hs(const __half* __restrict__ Ah, const __half* __restrict__ Al,
             const __half* __restrict__ Bh, const __half* __restrict__ Bl,
             float* __restrict__ C, int K, int ldb,
             const float* __restrict__ bias, float scale)
{
    extern __shared__ char smem[];
    const uint32_t sb = (uint32_t)__cvta_generic_to_shared(smem);

    const int tid = threadIdx.x, wid = tid >> 5, lane = tid & 31;
    const long bm = (long)blockIdx.y * 128;
    const long bn = (long)blockIdx.x * 128;

    // staging: 512 threads; row = tid>>2 (0..127), 2 chunks of 16B each
    const int srow = tid >> 2;
    const int sc0  = (tid & 3) * 2;
    uint32_t soff[2];
#pragma unroll
    for (int i = 0; i < 2; i++)
        soff[i] = SWZ((uint32_t)(srow * 128 + (sc0 + i) * 16));

    const int nk = K / 64;

    // prologue: stage buffer 0
    {
        const __half* pa  = Ah + (bm + srow) * (long)K + sc0 * 8;
        const __half* pl  = Al + (bm + srow) * (long)K + sc0 * 8;
        const __half* pb  = Bh + (bn + srow) * (long)ldb + sc0 * 8;
        const __half* pbl = Bl + (bn + srow) * (long)ldb + sc0 * 8;
#pragma unroll
        for (int i = 0; i < 2; i++) {
            CP16(sb + soff[i],         pa + i * 8);
            CP16(sb + 16384 + soff[i], pl + i * 8);
            CP16(sb + 32768 + soff[i], pb + i * 8);
            CP16(sb + 49152 + soff[i], pbl + i * 8);
        }
        CP_COMMIT();
    }

    float acc[2][4][4];
    uint32_t acc16[2][4][2];
#pragma unroll
    for (int a = 0; a < 2; a++)
#pragma unroll
        for (int b = 0; b < 4; b++) {
#pragma unroll
            for (int c = 0; c < 4; c++) acc[a][b][c] = 0.f;
            acc16[a][b][0] = 0u; acc16[a][b][1] = 0u;
        }

    const int m0 = (wid & 3) * 32;          // 4 warp-rows
    const int n0 = (wid >> 2) * 32;         // 4 warp-cols
    const int rA = lane & 15;
    const int cA = lane >> 4;
    const int rB = ((lane >> 1) & 8) + (lane & 7);
    const int cB = (lane >> 3) & 1;

    for (int kt = 0; kt < nk; ++kt) {
        const int s = kt & 1;
        CP_WAIT0();
        __syncthreads();

        if (kt + 1 < nk) {
            const uint32_t db = sb + (s ^ 1) * 65536;
            const __half* pa  = Ah + (bm + srow) * (long)K + (kt + 1) * 64 + sc0 * 8;
            const __half* pl  = Al + (bm + srow) * (long)K + (kt + 1) * 64 + sc0 * 8;
            const __half* pb  = Bh + (bn + srow) * (long)ldb + (kt + 1) * 64 + sc0 * 8;
            const __half* pbl = Bl + (bn + srow) * (long)ldb + (kt + 1) * 64 + sc0 * 8;
#pragma unroll
            for (int i = 0; i < 2; i++) {
                CP16(db + soff[i],         pa + i * 8);
                CP16(db + 16384 + soff[i], pl + i * 8);
                CP16(db + 32768 + soff[i], pb + i * 8);
                CP16(db + 49152 + soff[i], pbl + i * 8);
            }
            CP_COMMIT();
        }

        const uint32_t ba = sb + (uint32_t)s * 65536;
#pragma unroll
        for (int ks = 0; ks < 4; ks++) {
            uint32_t ah[2][4], al[2][4], bh[2][4], bl[2][4];
#pragma unroll
            for (int mt = 0; mt < 2; mt++) {
                const uint32_t addr = ba +
                    SWZ((uint32_t)((m0 + mt * 16 + rA) * 128 + (ks * 2 + cA) * 16));
                LDSM4(ah[mt], addr);
                LDSM4(al[mt], addr + 16384);
            }
#pragma unroll
            for (int p = 0; p < 2; p++) {
                const uint32_t addr = ba + 32768 +
                    SWZ((uint32_t)((n0 + p * 16 + rB) * 128 + (ks * 2 + cB) * 16));
                LDSM4(bh[p], addr);
                LDSM4(bl[p], addr + 16384);
            }
            // pass 1: hi*hi (fp32 acc)
#pragma unroll
            for (int mt = 0; mt < 2; mt++)
#pragma unroll
                for (int nt = 0; nt < 4; nt++) {
                    const int p = nt >> 1, q = (nt & 1) * 2;
                    MMA(acc[mt][nt], ah[mt], bh[p][q], bh[p][q + 1]);
                }
            // pass 2: hi*lo (fp16 acc)
#pragma unroll
            for (int mt = 0; mt < 2; mt++)
#pragma unroll
                for (int nt = 0; nt < 4; nt++) {
                    const int p = nt >> 1, q = (nt & 1) * 2;
                    MMA16(acc16[mt][nt], ah[mt], bl[p][q], bl[p][q + 1]);
                }
            // pass 3: lo*hi (fp16 acc)
#pragma unroll
            for (int mt = 0; mt < 2; mt++)
#pragma unroll
                for (int nt = 0; nt < 4; nt++) {
                    const int p = nt >> 1, q = (nt & 1) * 2;
                    MMA16(acc16[mt][nt], al[mt], bh[p][q], bh[p][q + 1]);
                }
        }
    }

    const int g = lane >> 2, t = lane & 3;
#pragma unroll
    for (int mt = 0; mt < 2; mt++) {
        const long r0 = bm + m0 + mt * 16 + g;
#pragma unroll
        for (int nt = 0; nt < 4; nt++) {
            const long col = bn + n0 + nt * 8 + 2 * t;
            const float2 u = h2f2(acc16[mt][nt][0]);
            const float2 w = h2f2(acc16[mt][nt][1]);
            float c0 = (acc[mt][nt][0] + u.x) * scale;
            float c1 = (acc[mt][nt][1] + u.y) * scale;
            float c2 = (acc[mt][nt][2] + w.x) * scale;
            float c3 = (acc[mt][nt][3] + w.y) * scale;
            if (bias) {
                const float b0 = __ldg(bias + col), b1 = __ldg(bias + col + 1);
                c0 += b0; c1 += b1; c2 += b0; c3 += b1;
            }
            *(float2*)(C + r0 * (long)D_ + col)       = make_float2(c0, c1);
            *(float2*)(C + (r0 + 8) * (long)D_ + col) = make_float2(c2, c3);
        }
    }
}

// ---------------------------------------------------------------------------
// Flash attention: per CTA = 128 Q rows x one (b,h).  (unchanged from R8)
// smem: Q 64K | Kbuf 2x32K | Vbuf 2x32K = 192K.
// ---------------------------------------------------------------------------
#define NKV (S_ / 64)     // 32 chunks

__global__ __launch_bounds__(256, 1)
void flash_kernel(const __half* __restrict__ Qh, const __half* __restrict__ Ql,
                  const __half* __restrict__ Kh, const __half* __restrict__ Kl,
                  const __half* __restrict__ Vth, const __half* __restrict__ Vtl,
                  __half* __restrict__ Ch, __half* __restrict__ Cl)
{
    extern __shared__ char smem[];
    const uint32_t sb = (uint32_t)__cvta_generic_to_shared(smem);

    const int tid = threadIdx.x, wid = tid >> 5, lane = tid & 31;
    const int qt = blockIdx.x;
    const int bh = blockIdx.y;
    const int b  = bh >> 4, h = bh & 15;

    const __half* Qhp = Qh + ((long)bh * S_ + (long)qt * 128) * DH;
    const __half* Qlp = Ql + ((long)bh * S_ + (long)qt * 128) * DH;
    const __half* Khp = Kh + (long)bh * S_ * DH;
    const __half* Klp = Kl + (long)bh * S_ * DH;
    const __half* Vhp = Vth + (long)bh * DH * S_;
    const __half* Vlp = Vtl + (long)bh * DH * S_;

    const uint32_t KBUF0 = 65536, VBUF0 = 131072;

    {
        const int r = tid >> 1, c0 = (tid & 1) * 8;
        const __half* s1 = Qhp + (long)r * DH;
        const __half* s2 = Qlp + (long)r * DH;
#pragma unroll
        for (int j = 0; j < 8; j++) {
            const int c = c0 + j;
            const uint32_t d = sb + ((c >= 8) ? 16384u : 0u) +
                               SWZ((uint32_t)(r * 128 + (c & 7) * 16));
            CP16(d,          s1 + c * 8);
            CP16(d + 32768u, s2 + c * 8);
        }
    }
    auto stageKV = [&](int it, uint32_t kdst, uint32_t vdst) {
        {
            const int r = tid >> 2, c0 = (tid & 3) * 4;
            const __half* s1 = Khp + ((long)it * 64 + r) * DH;
            const __half* s2 = Klp + ((long)it * 64 + r) * DH;
#pragma unroll
            for (int j = 0; j < 4; j++) {
                const int c = c0 + j;
                const uint32_t d = kdst + ((c >= 8) ? 8192u : 0u) +
                                   SWZ((uint32_t)(r * 128 + (c & 7) * 16));
                CP16(d,          s1 + c * 8);
                CP16(d + 16384u, s2 + c * 8);
            }
        }
        {
            const int dd = tid >> 1, c0 = (tid & 1) * 4;
            const __half* s1 = Vhp + (long)dd * S_ + it * 64;
            const __half* s2 = Vlp + (long)dd * S_ + it * 64;
#pragma unroll
            for (int j = 0; j < 4; j++) {
                const int c = c0 + j;
                const uint32_t d = vdst + SWZ((uint32_t)(dd * 128 + c * 16));
                CP16(d,          s1 + c * 8);
                CP16(d + 16384u, s2 + c * 8);
            }
        }
    };
    stageKV(0, sb + KBUF0, sb + VBUF0);
    CP_COMMIT();

    const int wm = wid * 16;
    const int rA = lane & 15;
    const int cA = lane >> 4;
    const int rB = ((lane >> 1) & 8) + (lane & 7);
    const int cB = (lane >> 3) & 1;
    const int g = lane >> 2, t = lane & 3;

    float o[16][4];
    uint32_t o16a[16][2], o16b[16][2];
#pragma unroll
    for (int i = 0; i < 16; i++) {
#pragma unroll
        for (int j = 0; j < 4; j++) o[i][j] = 0.f;
        o16a[i][0] = 0u; o16a[i][1] = 0u;
        o16b[i][0] = 0u; o16b[i][1] = 0u;
    }
    float m0 = -INFINITY, m1 = -INFINITY, l0 = 0.f, l1 = 0.f;

    for (int it = 0; it < NKV; ++it) {
        const int s = it & 1;
        CP_WAIT0();
        __syncthreads();
        if (it + 1 < NKV) {
            const int s2 = s ^ 1;
            stageKV(it + 1, sb + KBUF0 + s2 * 32768u, sb + VBUF0 + s2 * 32768u);
            CP_COMMIT();
        }

        const uint32_t kbuf = sb + KBUF0 + (uint32_t)s * 32768u;
        const uint32_t vbuf = sb + VBUF0 + (uint32_t)s * 32768u;

        float sa[8][4];
        uint32_t sa16[8][2];
#pragma unroll
        for (int i = 0; i < 8; i++) {
#pragma unroll
            for (int j = 0; j < 4; j++) sa[i][j] = 0.f;
            sa16[i][0] = 0u; sa16[i][1] = 0u;
        }

#pragma unroll
        for (int ks = 0; ks < 8; ks++) {
            uint32_t ah[4], al[4], bh[4][4], bl[4][4];
            const uint32_t qa = sb + (ks >> 2) * 16384u +
                SWZ((uint32_t)((wm + rA) * 128 + ((ks & 3) * 2 + cA) * 16));
            LDSM4(ah, qa);
            LDSM4(al, qa + 32768u);
            const uint32_t kb2 = kbuf + (ks >> 2) * 8192u;
#pragma unroll
            for (int p = 0; p < 4; p++) {
                const uint32_t addr = kb2 +
                    SWZ((uint32_t)((p * 16 + rB) * 128 + ((ks & 3) * 2 + cB) * 16));
                LDSM4(bh[p], addr);
                LDSM4(bl[p], addr + 16384u);
            }
#pragma unroll
            for (int nt = 0; nt < 8; nt++) {
                const int p = nt >> 1, q = (nt & 1) * 2;
                MMA(sa[nt], ah, bh[p][q], bh[p][q + 1]);
            }
#pragma unroll
            for (int nt = 0; nt < 8; nt++) {
                const int p = nt >> 1, q = (nt & 1) * 2;
                MMA16(sa16[nt], ah, bl[p][q], bl[p][q + 1]);
            }
#pragma unroll
            for (int nt = 0; nt < 8; nt++) {
                const int p = nt >> 1, q = (nt & 1) * 2;
                MMA16(sa16[nt], al, bh[p][q], bh[p][q + 1]);
            }
        }

#pragma unroll
        for (int nt = 0; nt < 8; nt++) {
            const float2 u = h2f2(sa16[nt][0]);
            const float2 w = h2f2(sa16[nt][1]);
            sa[nt][0] += u.x; sa[nt][1] += u.y;
            sa[nt][2] += w.x; sa[nt][3] += w.y;
        }

        float nm0 = sa[0][0], nm1 = sa[0][2];
#pragma unroll
        for (int nt = 0; nt < 8; nt++) {
            nm0 = fmaxf(nm0, fmaxf(sa[nt][0], sa[nt][1]));
            nm1 = fmaxf(nm1, fmaxf(sa[nt][2], sa[nt][3]));
        }
        nm0 = fmaxf(nm0, __shfl_xor_sync(0xFFFFFFFFu, nm0, 1));
        nm0 = fmaxf(nm0, __shfl_xor_sync(0xFFFFFFFFu, nm0, 2));
        nm1 = fmaxf(nm1, __shfl_xor_sync(0xFFFFFFFFu, nm1, 1));
        nm1 = fmaxf(nm1, __shfl_xor_sync(0xFFFFFFFFu, nm1, 2));

        const float mn0 = fmaxf(m0, nm0), mn1 = fmaxf(m1, nm1);
        const float al0 = exp2f(m0 - mn0), al1 = exp2f(m1 - mn1);
        m0 = mn0; m1 = mn1;

        float rs0 = 0.f, rs1 = 0.f;
#pragma unroll
        for (int nt = 0; nt < 8; nt++) {
            sa[nt][0] = exp2f(sa[nt][0] - m0);
            sa[nt][1] = exp2f(sa[nt][1] - m0);
            sa[nt][2] = exp2f(sa[nt][2] - m1);
            sa[nt][3] = exp2f(sa[nt][3] - m1);
            rs0 += sa[nt][0] + sa[nt][1];
            rs1 += sa[nt][2] + sa[nt][3];
        }
        rs0 += __shfl_xor_sync(0xFFFFFFFFu, rs0, 1);
        rs0 += __shfl_xor_sync(0xFFFFFFFFu, rs0, 2);
        rs1 += __shfl_xor_sync(0xFFFFFFFFu, rs1, 1);
        rs1 += __shfl_xor_sync(0xFFFFFFFFu, rs1, 2);
        l0 = l0 * al0 + rs0;
        l1 = l1 * al1 + rs1;

        {
            const __half2 a0 = __half2half2(__float2half(al0));
            const __half2 a1 = __half2half2(__float2half(al1));
#pragma unroll
            for (int nt = 0; nt < 16; nt++) {
                o[nt][0] *= al0; o[nt][1] *= al0;
                o[nt][2] *= al1; o[nt][3] *= al1;
                __half2 ta0 = __hmul2(*(__half2*)&o16a[nt][0], a0);
                __half2 ta1 = __hmul2(*(__half2*)&o16a[nt][1], a1);
                __half2 tb0 = __hmul2(*(__half2*)&o16b[nt][0], a0);
                __half2 tb1 = __hmul2(*(__half2*)&o16b[nt][1], a1);
                o16a[nt][0] = *(uint32_t*)&ta0;
                o16a[nt][1] = *(uint32_t*)&ta1;
                o16b[nt][0] = *(uint32_t*)&tb0;
                o16b[nt][1] = *(uint32_t*)&tb1;
            }
        }

#pragma unroll
        for (int kb = 0; kb < 4; kb++) {
            uint32_t aPh[4], aPl[4];
            {
                const float p00 = sa[2 * kb][0],     p01 = sa[2 * kb][1];
                const float p10 = sa[2 * kb][2],     p11 = sa[2 * kb][3];
                const float q00 = sa[2 * kb + 1][0], q01 = sa[2 * kb + 1][1];
                const float q10 = sa[2 * kb + 1][2], q11 = sa[2 * kb + 1][3];
                __half hA, lA, hB, lB;
                split2(p00, hA, lA); split2(p01, hB, lB);
                aPh[0] = packh2(hA, hB); aPl[0] = packh2(lA, lB);
                split2(p10, hA, lA); split2(p11, hB, lB);
                aPh[1] = packh2(hA, hB); aPl[1] = packh2(lA, lB);
                split2(q00, hA, lA); split2(q01, hB, lB);
                aPh[2] = packh2(hA, hB); aPl[2] = packh2(lA, lB);
                split2(q10, hA, lA); split2(q11, hB, lB);
                aPh[3] = packh2(hA, hB); aPl[3] = packh2(lA, lB);
            }
#pragma unroll
            for (int pp = 0; pp < 8; pp++) {
                uint32_t vb[4], vbl[4];
                const uint32_t addr = vbuf +
                    SWZ((uint32_t)((pp * 16 + rB) * 128 + (kb * 2 + cB) * 16));
                LDSM4(vb, addr);
                LDSM4(vbl, addr + 16384u);
                MMA(o[pp * 2], aPh, vb[0], vb[1]);
                MMA16(o16a[pp * 2], aPh, vbl[0], vbl[1]);
                MMA16(o16b[pp * 2], aPl, vb[0], vb[1]);
                MMA(o[pp * 2 + 1], aPh, vb[2], vb[3]);
                MMA16(o16a[pp * 2 + 1], aPh, vbl[2], vbl[3]);
                MMA16(o16b[pp * 2 + 1], aPl, vb[2], vb[3]);
            }
        }
    }

    const float r0i = 1.0f / l0, r1i = 1.0f / l1;
    const long row0 = (long)b * S_ + (long)qt * 128 + wm + g;
    const long row1 = row0 + 8;
#pragma unroll
    for (int nt = 0; nt < 16; nt++) {
        const long col = (long)h * DH + nt * 8 + 2 * t;
        const float2 ua = h2f2(o16a[nt][0]);
        const float2 wa = h2f2(o16a[nt][1]);
        const float2 ub = h2f2(o16b[nt][0]);
        const float2 wb = h2f2(o16b[nt][1]);
        const float c00 = (o[nt][0] + ua.x + ub.x) * r0i;
        const float c01 = (o[nt][1] + ua.y + ub.y) * r0i;
        const float c10 = (o[nt][2] + wa.x + wb.x) * r1i;
        const float c11 = (o[nt][3] + wa.y + wb.y) * r1i;
        __half hA, lA, hB, lB;
        split2(c00, hA, lA); split2(c01, hB, lB);
        *(uint32_t*)(Ch + row0 * D_ + col) = packh2(hA, hB);
        *(uint32_t*)(Cl + row0 * D_ + col) = packh2(lA, lB);
        split2(c10, hA, lA); split2(c11, hB, lB);
        *(uint32_t*)(Ch + row1 * D_ + col) = packh2(hA, hB);
        *(uint32_t*)(Cl + row1 * D_ + col) = packh2(lA, lB);
    }
}

// ---------------------------------------------------------------------------
// Fused fp32 -> fp16 hi/lo split for x + 4 weight matrices (one launch).
// ---------------------------------------------------------------------------
__global__ __launch_bounds__(256)
void split_all_kernel(const float* __restrict__ x,
                      const float* __restrict__ qw, const float* __restrict__ kw,
                      const float* __restrict__ vw, const float* __restrict__ ow)
{
    const float* src;
    __half *oh, *ol;
    long n;
    switch (blockIdx.y) {
        case 0: src = x;  oh = g_xh;  ol = g_xl;  n = (long)MROWS * D_; break;
        case 1: src = qw; oh = g_qwh; ol = g_qwl; n = (long)D_ * D_;    break;
        case 2: src = kw; oh = g_kwh; ol = g_kwl; n = (long)D_ * D_;    break;
        case 3: src = vw; oh = g_vwh; ol = g_vwl; n = (long)D_ * D_;    break;
        default: src = ow; oh = g_owh; ol = g_owl; n = (long)D_ * D_;   break;
    }
    const long i = ((long)blockIdx.x * blockDim.x + threadIdx.x) * 4;
    if (i >= n) return;
    float4 v = *(const float4*)(src + i);
    __half h0, l0, h1, l1, h2, l2, h3, l3;
    split2(v.x, h0, l0); split2(v.y, h1, l1);
    split2(v.z, h2, l2); split2(v.w, h3, l3);
    *(uint32_t*)(oh + i)     = packh2(h0, h1);
    *(uint32_t*)(oh + i + 2) = packh2(h2, h3);
    *(uint32_t*)(ol + i)     = packh2(l0, l1);
    *(uint32_t*)(ol + i + 2) = packh2(l2, l3);
}

// ---------------------------------------------------------------------------
// Fused RoPE(+permute, split) for q,k  AND  V transpose/split.
// ---------------------------------------------------------------------------
#define RB ((B_ * H_ * S_ * (DH / 2)) / 256)      // 16384 rope blocks
#define VB ((S_ / 32) * (DH / 32) * (B_ * H_))    // 8192 vtrans blocks

__global__ __launch_bounds__(256)
void rope_vtrans_kernel()
{
    __shared__ float tile[32][33];
    const int bid = blockIdx.x;

    if (bid < RB) {
        const int HALF = DH / 2;
        const long idx = (long)bid * 256 + threadIdx.x;

        const int j = (int)(idx % HALF);
        const int s = (int)((idx / HALF) % S_);
        const int h = (int)((idx / ((long)HALF * S_)) % H_);
        const int b = (int)(idx / ((long)HALF * S_ * H_));

        const long off_in  = ((long)(b * S_ + s)) * D_ + h * DH + j;
        const long off_out = (((long)(b * H_ + h) * S_) + s) * DH + j;

        const float inv = expf(-(float)j * (9.210340371976184f / 64.0f));
        const float th  = (float)s * inv;
        const float c  = cosf(th);
        const float sn = sinf(th);

        const float QS = 0.08838834764831845f * 1.4426950408889634f; // scale*log2e

        {
            const float x1 = g_tq[off_in];
            const float x2 = g_tq[off_in + HALF];
            const float o1 = (x1 * c - x2 * sn) * QS;
            const float o2 = (x2 * c + x1 * sn) * QS;
            __half hh, hl;
            split2(o1, hh, hl); g_qh[off_out] = hh;        g_ql[off_out] = hl;
            split2(o2, hh, hl); g_qh[off_out + HALF] = hh; g_ql[off_out + HALF] = hl;
        }
        {
            const float x1 = g_tk[off_in];
            const float x2 = g_tk[off_in + HALF];
            const float o1 = x1 * c - x2 * sn;
            const float o2 = x2 * c + x1 * sn;
            __half hh, hl;
            split2(o1, hh, hl); g_kh[off_out] = hh;        g_kl[off_out] = hl;
            split2(o2, hh, hl); g_kh[off_out + HALF] = hh; g_kl[off_out + HALF] = hl;
        }
    } else {
        const int vb = bid - RB;
        const int sblk = vb % (S_ / 32);
        const int dblk = (vb / (S_ / 32)) % (DH / 32);
        const int bhz  = vb / ((S_ / 32) * (DH / 32));
        const int b = bhz >> 4, h = bhz & 15;
        const int s0 = sblk * 32, d0 = dblk * 32;
        const int tx = threadIdx.x & 31, ty = threadIdx.x >> 5;

#pragma unroll
        for (int r = 0; r < 4; r++) {
            const int s = s0 + ty + r * 8;
            tile[ty + r * 8][tx] =
                g_tv[((long)b * S_ + s) * D_ + h * DH + d0 + tx];
        }
        __syncthreads();

#pragma unroll
        for (int r = 0; r < 4; r++) {
            const int d = d0 + ty + r * 8;
            const float v = tile[tx][ty + r * 8];
            __half hh, hl;
            split2(v, hh, hl);
            const long off = ((long)bhz * DH + d) * S_ + s0 + tx;
            g_vth[off] = hh;
            g_vtl[off] = hl;
        }
    }
}

// ---------------------------------------------------------------------------
// Launch
// ---------------------------------------------------------------------------
extern "C" void kernel_launch(void* const* d_in, const int* in_sizes, int n_in,
                              void* d_out, int out_size)
{
    const float* x  = (const float*)d_in[0];
    const float* qw = (const float*)d_in[1];
    const float* kw = (const float*)d_in[2];
    const float* vw = (const float*)d_in[3];
    const float* qb = (const float*)d_in[4];
    const float* kb = (const float*)d_in[5];
    const float* vb = (const float*)d_in[6];
    const float* ow = (const float*)d_in[7];
    const float* ob = (const float*)d_in[8];
    float* out = (float*)d_out;

    float *tq, *tk, *tv;
    __half *xh, *xl, *qwh, *qwl, *kwh, *kwl, *vwh, *vwl, *owh, *owl;
    __half *qh, *ql, *kh, *kl, *vth, *vtl, *ctxh, *ctxl;
    cudaGetSymbolAddress((void**)&tq,  g_tq);
    cudaGetSymbolAddress((void**)&tk,  g_tk);
    cudaGetSymbolAddress((void**)&tv,  g_tv);
    cudaGetSymbolAddress((void**)&xh,  g_xh);
    cudaGetSymbolAddress((void**)&xl,  g_xl);
    cudaGetSymbolAddress((void**)&qwh, g_qwh);
    cudaGetSymbolAddress((void**)&qwl, g_qwl);
    cudaGetSymbolAddress((void**)&kwh, g_kwh);
    cudaGetSymbolAddress((void**)&kwl, g_kwl);
    cudaGetSymbolAddress((void**)&vwh, g_vwh);
    cudaGetSymbolAddress((void**)&vwl, g_vwl);
    cudaGetSymbolAddress((void**)&owh, g_owh);
    cudaGetSymbolAddress((void**)&owl, g_owl);
    cudaGetSymbolAddress((void**)&qh,  g_qh);
    cudaGetSymbolAddress((void**)&ql,  g_ql);
    cudaGetSymbolAddress((void**)&kh,  g_kh);
    cudaGetSymbolAddress((void**)&kl,  g_kl);
    cudaGetSymbolAddress((void**)&vth, g_vth);
    cudaGetSymbolAddress((void**)&vtl, g_vtl);
    cudaGetSymbolAddress((void**)&ctxh, g_ctxh);
    cudaGetSymbolAddress((void**)&ctxl, g_ctxl);

    const int SMEM_G = 131072;
    const int SMEM_F = 196608;
    cudaFuncSetAttribute(gemm_hs,      cudaFuncAttributeMaxDynamicSharedMemorySize, SMEM_G);
    cudaFuncSetAttribute(flash_kernel, cudaFuncAttributeMaxDynamicSharedMemorySize, SMEM_F);

    const dim3 blk(256);
    const dim3 blk_g(512);

    // 0: split fp32 inputs to fp16 hi/lo (one fused launch)
    {
        const long nx = (long)MROWS * D_;
        dim3 grid((unsigned)(nx / 4 / 256), 5);
        split_all_kernel<<<grid, blk>>>(x, qw, kw, vw, ow);
    }

    // 1-3: Q/K/V projections (M=4096, N=2048, K=2048), fp32 out
    {
        dim3 grid(D_ / 128, MROWS / 128, 1);
        gemm_hs<<<grid, blk_g, SMEM_G>>>(xh, xl, qwh, qwl, tq, D_, D_, qb, 1.0f);
        gemm_hs<<<grid, blk_g, SMEM_G>>>(xh, xl, kwh, kwl, tk, D_, D_, kb, 1.0f);
        gemm_hs<<<grid, blk_g, SMEM_G>>>(xh, xl, vwh, vwl, tv, D_, D_, vb, 1.0f);
    }

    // 4: RoPE (q,k) + permute/split  AND  V transpose/split (one launch)
    rope_vtrans_kernel<<<RB + VB, blk>>>();

    // 5: fused flash attention -> ctx split fp16 [B,S,D]
    {
        dim3 grid(S_ / 128, B_ * H_);
        flash_kernel<<<grid, blk, SMEM_F>>>(qh, ql, kh, kl, vth, vtl, ctxh, ctxl);
    }

    // 6: out = ctx @ out_w^T + out_b (fp32 out)
    {
        dim3 grid(D_ / 128, MROWS / 128, 1);
        gemm_hs<<<grid, blk_g, SMEM_G>>>(ctxh, ctxl, owh, owl, out, D_, D_, ob, 1.0f);
    }
}